// round 12
// baseline (speedup 1.0000x reference)
#include <cuda_runtime.h>
#include <cuda_fp16.h>
#include <math.h>
#include <stdint.h>

#define NN 50000
#define NE 640000
#define NNP 50048   // padded rows (GEMM tiles read up to 782*64)

// ---------------- scratch (static device globals; no allocation) ----------------
__device__ __half g_aggh[NNP * 128];        // fp16 aggregate buffer (width 64 or 128)
__device__ __half g_tsh[NNP * 128];         // fp16 layer-2 ts output
__device__ __half g_xh[NNP * 64];           // fp16 copy of x
__device__ __half g_h0h[NNP * 128];         // fp16 h0
__device__ __half g_h1h[NNP * 128];         // fp16 h1
__device__ float  g_invdeg[NN];
__device__ int    g_cnt[NN];
__device__ int    g_rowptr[NN];
__device__ int    g_cursor[NN];
__device__ int    g_srcidx[NE];
__device__ int    g_total;
__device__ int    g_is64;
// transposed fp16 weights: slots 0-3 = Wl0,Wr0,Wl1,Wr1 ([N][K] k-major);
// slot 4 = concat [Wl2 rows 0-63 | Wr2 rows 64-127], K=128
__device__ __half g_wt[5][16384];

// ---------------- helpers ----------------
__device__ __forceinline__ uint32_t smem_u32(const void* p) {
    uint32_t a;
    asm("{ .reg .u64 t; cvta.to.shared.u64 t, %1; cvt.u32.u64 %0, t; }" : "=r"(a) : "l"(p));
    return a;
}
__device__ __forceinline__ void ldsm4(uint32_t& r0, uint32_t& r1, uint32_t& r2, uint32_t& r3,
                                      uint32_t addr) {
    asm volatile("ldmatrix.sync.aligned.m8n8.x4.shared.b16 {%0,%1,%2,%3}, [%4];"
                 : "=r"(r0), "=r"(r1), "=r"(r2), "=r"(r3) : "r"(addr));
}
__device__ __forceinline__ void mma_fp16(float* d, const uint32_t* a, const uint32_t* b) {
    asm volatile(
        "mma.sync.aligned.m16n8k16.row.col.f32.f16.f16.f32 "
        "{%0,%1,%2,%3}, {%4,%5,%6,%7}, {%8,%9}, {%0,%1,%2,%3};"
        : "+f"(d[0]), "+f"(d[1]), "+f"(d[2]), "+f"(d[3])
        : "r"(a[0]), "r"(a[1]), "r"(a[2]), "r"(a[3]), "r"(b[0]), "r"(b[1]));
}
__device__ __forceinline__ int sw128(int byte) { return byte ^ ((byte >> 3) & 0x70); }
__device__ __forceinline__ void cpasync16(uint32_t dst, const void* src) {
    asm volatile("cp.async.cg.shared.global [%0], [%1], 16;" :: "r"(dst), "l"(src));
}
#define CP_COMMIT() asm volatile("cp.async.commit_group;" ::: "memory")
#define CP_WAIT0()  asm volatile("cp.async.wait_group 0;" ::: "memory")

// ---------------- detect edge dtype + zero degree counters (merged) ----------------
__global__ void detect_zero(const int* __restrict__ w) {
    int i = blockIdx.x * blockDim.x + threadIdx.x;
    if (i < NN) g_cnt[i] = 0;
    if (i == 0) g_total = 0;
    if (blockIdx.x == 0) {
        __shared__ int flag;
        if (threadIdx.x == 0) flag = 0;
        __syncthreads();
        if (w[threadIdx.x * 2 + 1] != 0) atomicExch(&flag, 1);
        __syncthreads();
        if (threadIdx.x == 0) g_is64 = (flag == 0) ? 1 : 0;
    }
}

__device__ __forceinline__ int2 load_edge(const void* __restrict__ ei, int e) {
    int2 r;
    if (g_is64) {
        const long long* p = (const long long*)ei;
        r.x = (int)p[e];
        r.y = (int)p[NE + e];
    } else {
        const int* p = (const int*)ei;
        r.x = p[e];
        r.y = p[NE + e];
    }
    return r;
}

__global__ void count_deg(const void* __restrict__ ei) {
    int e = blockIdx.x * blockDim.x + threadIdx.x;
    if (e >= NE) return;
    int2 sd = load_edge(ei, e);
    atomicAdd(&g_cnt[sd.y], 1);
}

// unordered CSR range assignment: rowptr[i] = atomicAdd(total, cnt[i])
// (warp-aggregated by ptxas; per-node lists stay contiguous, order is irrelevant)
__global__ void assign() {
    int i = blockIdx.x * blockDim.x + threadIdx.x;
    if (i >= NN) return;
    int c = g_cnt[i];
    int r = atomicAdd(&g_total, c);
    g_rowptr[i] = r;
    g_cursor[i] = r;
    g_invdeg[i] = 1.0f / fmaxf((float)c, 1.0f);
}

__global__ void fill_csr(const void* __restrict__ ei) {
    int e = blockIdx.x * blockDim.x + threadIdx.x;
    if (e >= NE) return;
    int2 sd = load_edge(ei, e);
    int pos = atomicAdd(&g_cursor[sd.y], 1);
    g_srcidx[pos] = sd.x;
}

// ---------------- prep: weights transpose->fp16 (blocks 0-47) + x->fp16 (blocks 48+) ----------------
__global__ void prep(const float* __restrict__ x,
                     const float* W0, const float* W1, const float* W2,
                     const float* W3, const float* W4, const float* W5) {
    if (blockIdx.x < 48) {
        int b    = blockIdx.x >> 3;   // slot select 0..5
        int part = blockIdx.x & 7;
        const float* W;
        int K, N, slot, rofs;
        switch (b) {
            case 0: W = W0; K = 64;  N = 128; slot = 0; rofs = 0; break;
            case 1: W = W1; K = 64;  N = 128; slot = 1; rofs = 0; break;
            case 2: W = W2; K = 128; N = 128; slot = 2; rofs = 0; break;
            case 3: W = W3; K = 128; N = 128; slot = 3; rofs = 0; break;
            case 4: W = W4; K = 128; N = 64;  slot = 4; rofs = 0; break;   // Wl2 -> rows 0-63
            default: W = W5; K = 128; N = 64; slot = 4; rofs = 64; break;  // Wr2 -> rows 64-127
        }
        __half* dh = g_wt[slot] + rofs * 128;
        int total = K * N;
        for (int i = part * blockDim.x + threadIdx.x; i < total; i += 8 * blockDim.x) {
            int n = i / K, k = i % K;
            dh[i] = __float2half_rn(W[k * N + n]);
        }
    } else {
        int i = (blockIdx.x - 48) * blockDim.x + threadIdx.x;
        int stride = (gridDim.x - 48) * blockDim.x;
        for (; i < NN * 64; i += stride) g_xh[i] = __float2half_rn(x[i]);
    }
}

// ---------------- CSR mean-aggregation, 16B loads: LPN lanes/node, lane owns 8 halves ----------------
template <int LPN>   // C = LPN * 8 halves
__global__ void agg_f16(const __half* __restrict__ feat, __half* __restrict__ out) {
    int gid  = blockIdx.x * blockDim.x + threadIdx.x;
    int node = gid / LPN;
    int lane = gid % LPN;
    if (node >= NN) return;
    const int  C   = LPN * 8;
    const int* idx = g_srcidx + g_rowptr[node];
    int        n   = g_cnt[node];
    float acc[8] = {0.f, 0.f, 0.f, 0.f, 0.f, 0.f, 0.f, 0.f};
    int j = 0;
    for (; j + 2 <= n; j += 2) {
        int s0 = idx[j], s1 = idx[j + 1];
        uint4 v0 = *(const uint4*)(feat + (size_t)s0 * C + lane * 8);
        uint4 v1 = *(const uint4*)(feat + (size_t)s1 * C + lane * 8);
        const uint32_t* w0 = (const uint32_t*)&v0;
        const uint32_t* w1 = (const uint32_t*)&v1;
#pragma unroll
        for (int k = 0; k < 4; k++) {
            float2 f0 = __half22float2(*(const __half2*)&w0[k]);
            float2 f1 = __half22float2(*(const __half2*)&w1[k]);
            acc[2 * k + 0] += f0.x + f1.x;
            acc[2 * k + 1] += f0.y + f1.y;
        }
    }
    if (j < n) {
        uint4 v0 = *(const uint4*)(feat + (size_t)idx[j] * C + lane * 8);
        const uint32_t* w0 = (const uint32_t*)&v0;
#pragma unroll
        for (int k = 0; k < 4; k++) {
            float2 f0 = __half22float2(*(const __half2*)&w0[k]);
            acc[2 * k + 0] += f0.x;
            acc[2 * k + 1] += f0.y;
        }
    }
    float s = g_invdeg[node];
    uint4 o;
    uint32_t* ow = (uint32_t*)&o;
#pragma unroll
    for (int k = 0; k < 4; k++) {
        __half2 h = __float22half2_rn(make_float2(acc[2 * k] * s, acc[2 * k + 1] * s));
        ow[k] = *(uint32_t*)&h;
    }
    *(uint4*)(out + (size_t)node * C + lane * 8) = o;
}

// ---------------- pipelined warp-MMA GEMM, pure fp16 ----------------
// DUAL: out = A1 @ BL^T + A2 @ BR^T (+bias)(relu);  !DUAL: out = A1 @ BL^T
template <int KSRC, bool DUAL, bool RELU, bool BIAS>
__global__ __launch_bounds__(256, 2) void gemm_f16(
    const __half* __restrict__ A1, const __half* __restrict__ A2,
    const __half* __restrict__ BL, const __half* __restrict__ BR,
    const float* __restrict__ bias, __half* __restrict__ out) {
    extern __shared__ char smem[];
    // per-buffer: A 8K @0, B 16K @8192; buffer stride 24KB; total 48KB
    constexpr int BUF = 24576, BO = 8192;

    uint32_t sb = smem_u32(smem);
    const int tid = threadIdx.x, wid = tid >> 5, lid = tid & 31;
    const int wm = wid & 3, wn = wid >> 2;   // 4 x 2 warp grid over 64 x 128
    const int m0 = blockIdx.x * 64;

    constexpr int KH  = KSRC / 64;
    constexpr int NPH = DUAL ? 2 * KH : KH;

    float acc[8][4];
#pragma unroll
    for (int j = 0; j < 8; j++)
#pragma unroll
        for (int c = 0; c < 4; c++) acc[j][c] = 0.0f;

    auto gload = [&](int p) {
        const __half* A = (p < KH) ? A1 : A2;
        const __half* B = (p < KH) ? BL : BR;
        int kofs = (p % KH) * 64;
        int bb   = (p & 1) * BUF;
#pragma unroll
        for (int i = 0; i < 2; i++) {
            int idx = tid + i * 256;       // 0..511
            int r   = idx >> 3;            // row 0..63
            int c8  = idx & 7;
            int sw  = sw128(r * 128 + c8 * 16);
            cpasync16(sb + bb + sw, A + (size_t)(m0 + r) * KSRC + kofs + c8 * 8);
        }
#pragma unroll
        for (int i = 0; i < 4; i++) {
            int idx = tid + i * 256;       // 0..1023
            int r   = idx >> 3;            // row 0..127
            int c8  = idx & 7;
            int sw  = sw128(r * 128 + c8 * 16);
            cpasync16(sb + bb + BO + sw, B + (size_t)r * KSRC + kofs + c8 * 8);
        }
        CP_COMMIT();
    };

    auto compute = [&](int p) {
        int bb = (p & 1) * BUF;
#pragma unroll
        for (int ks = 0; ks < 4; ks++) {
            int k0b = ks * 32;
            uint32_t ah[4];
            {
                int mrow = wm * 16 + (lid & 15);
                int sw   = sw128(mrow * 128 + k0b + (lid >> 4) * 16);
                ldsm4(ah[0], ah[1], ah[2], ah[3], sb + bb + sw);
            }
#pragma unroll
            for (int ntp = 0; ntp < 4; ntp++) {
                int nrow = wn * 64 + ntp * 16 + ((lid >> 4) & 1) * 8 + (lid & 7);
                int sw   = sw128(nrow * 128 + k0b + ((lid >> 3) & 1) * 16);
                uint32_t bh[4];
                ldsm4(bh[0], bh[1], bh[2], bh[3], sb + bb + BO + sw);
#pragma unroll
                for (int j = 0; j < 2; j++)
                    mma_fp16(acc[ntp * 2 + j], ah, bh + 2 * j);
            }
        }
    };

    gload(0);
    CP_WAIT0();
    __syncthreads();
#pragma unroll 1
    for (int p = 0; p < NPH; p++) {
        if (p + 1 < NPH) gload(p + 1);
        compute(p);
        CP_WAIT0();
        __syncthreads();
    }

    // ---- epilogue (fp16 out) ----
    const int r  = lid >> 2;
    const int c2 = (lid & 3) * 2;
    int row0 = m0 + wm * 16 + r;
    int row1 = row0 + 8;
#pragma unroll
    for (int nt = 0; nt < 8; nt++) {
        int col = wn * 64 + nt * 8 + c2;
        float bx = BIAS ? __ldg(bias + col) : 0.f;
        float by = BIAS ? __ldg(bias + col + 1) : 0.f;
        float2 o0 = make_float2(acc[nt][0] + bx, acc[nt][1] + by);
        float2 o1 = make_float2(acc[nt][2] + bx, acc[nt][3] + by);
        if (RELU) {
            o0.x = fmaxf(o0.x, 0.f); o0.y = fmaxf(o0.y, 0.f);
            o1.x = fmaxf(o1.x, 0.f); o1.y = fmaxf(o1.y, 0.f);
        }
        if (row0 < NN) *(__half2*)(out + (size_t)row0 * 128 + col) = __float22half2_rn(o0);
        if (row1 < NN) *(__half2*)(out + (size_t)row1 * 128 + col) = __float22half2_rn(o1);
    }
}

// ---------------- layer-2 finalize + classifier (fused), warp per node ----------------
// ts: [NN][128] fp16; cols 0-63 = t = h1@Wl2 (to aggregate), cols 64-127 = s = h1@Wr2
__global__ void finalize_classifier(const __half* __restrict__ ts, const float* __restrict__ b2,
                                    const float* __restrict__ Wc1, const float* __restrict__ bc1,
                                    const float* __restrict__ Wc2, const float* __restrict__ bc2,
                                    float* __restrict__ out) {
    int gid  = blockIdx.x * blockDim.x + threadIdx.x;
    int node = gid >> 5;
    int lane = gid & 31;
    if (node >= NN) return;

    const int* idx = g_srcidx + g_rowptr[node];
    int n = g_cnt[node];
    float2 acc = make_float2(0.f, 0.f);
    int j = 0;
    for (; j + 4 <= n; j += 4) {
        int s0 = idx[j], s1 = idx[j + 1], s2 = idx[j + 2], s3 = idx[j + 3];
        float2 v0 = __half22float2(*(const __half2*)(ts + (size_t)s0 * 128 + lane * 2));
        float2 v1 = __half22float2(*(const __half2*)(ts + (size_t)s1 * 128 + lane * 2));
        float2 v2 = __half22float2(*(const __half2*)(ts + (size_t)s2 * 128 + lane * 2));
        float2 v3 = __half22float2(*(const __half2*)(ts + (size_t)s3 * 128 + lane * 2));
        acc.x += (v0.x + v1.x) + (v2.x + v3.x);
        acc.y += (v0.y + v1.y) + (v2.y + v3.y);
    }
    for (; j < n; j++) {
        float2 v = __half22float2(*(const __half2*)(ts + (size_t)idx[j] * 128 + lane * 2));
        acc.x += v.x; acc.y += v.y;
    }
    float sc = g_invdeg[node];
    float2 s = __half22float2(*(const __half2*)(ts + (size_t)node * 128 + 64 + lane * 2));
    float vx = acc.x * sc + s.x + __ldg(b2 + lane * 2);
    float vy = acc.y * sc + s.y + __ldg(b2 + lane * 2 + 1);

    float h = __ldg(bc1 + lane);
#pragma unroll
    for (int k = 0; k < 32; k++) {
        float ax = __shfl_sync(0xffffffffu, vx, k);
        float ay = __shfl_sync(0xffffffffu, vy, k);
        h = fmaf(ax, __ldg(Wc1 + (2 * k) * 32 + lane), h);
        h = fmaf(ay, __ldg(Wc1 + (2 * k + 1) * 32 + lane), h);
    }
    h = fmaxf(h, 0.0f);

    float p = h * __ldg(Wc2 + lane);
#pragma unroll
    for (int o = 16; o > 0; o >>= 1) p += __shfl_xor_sync(0xffffffffu, p, o);

    if (lane == 0) out[node] = 1.0f / (1.0f + expf(-(p + bc2[0])));
}

// ---------------- launch ----------------
extern "C" void kernel_launch(void* const* d_in, const int* in_sizes, int n_in,
                              void* d_out, int out_size) {
    const float* x   = (const float*)d_in[0];
    const void*  ei  = d_in[1];
    const float* Wl0 = (const float*)d_in[2];
    const float* Wr0 = (const float*)d_in[3];
    const float* b0  = (const float*)d_in[4];
    const float* Wl1 = (const float*)d_in[5];
    const float* Wr1 = (const float*)d_in[6];
    const float* b1  = (const float*)d_in[7];
    const float* Wl2 = (const float*)d_in[8];
    const float* Wr2 = (const float*)d_in[9];
    const float* b2  = (const float*)d_in[10];
    const float* Wc1 = (const float*)d_in[11];
    const float* bc1 = (const float*)d_in[12];
    const float* Wc2 = (const float*)d_in[13];
    const float* bc2 = (const float*)d_in[14];
    float* out = (float*)d_out;

    __half *aggh, *tsh, *xh, *h0h, *h1h, *wt;
    cudaGetSymbolAddress((void**)&aggh, g_aggh);
    cudaGetSymbolAddress((void**)&tsh, g_tsh);
    cudaGetSymbolAddress((void**)&xh, g_xh);
    cudaGetSymbolAddress((void**)&h0h, g_h0h);
    cudaGetSymbolAddress((void**)&h1h, g_h1h);
    cudaGetSymbolAddress((void**)&wt, g_wt);

    const int SMEM_SZ = 2 * 24576;  // 48KB (double-buffered 24KB stages)
    cudaFuncSetAttribute((void*)gemm_f16<64, true, true, true>,
                         cudaFuncAttributeMaxDynamicSharedMemorySize, SMEM_SZ);
    cudaFuncSetAttribute((void*)gemm_f16<128, true, true, true>,
                         cudaFuncAttributeMaxDynamicSharedMemorySize, SMEM_SZ);
    cudaFuncSetAttribute((void*)gemm_f16<128, false, false, false>,
                         cudaFuncAttributeMaxDynamicSharedMemorySize, SMEM_SZ);

    // CSR build (shared by all 3 layers) — unordered range assignment, no scans
    detect_zero<<<(NN + 255) / 256, 256>>>((const int*)ei);
    count_deg<<<(NE + 255) / 256, 256>>>(ei);
    assign<<<(NN + 255) / 256, 256>>>();
    fill_csr<<<(NE + 255) / 256, 256>>>(ei);

    // weights -> fp16 transposed + x -> fp16, one kernel
    prep<<<48 + 1024, 256>>>(x, Wl0, Wr0, Wl1, Wr1, Wl2, Wr2);

    const int GEMM_GRID = (NNP + 63) / 64;  // 782

    // layer 0: agg(x_h) fp16 + x_h self -> h0 fp16   (C=64 -> LPN=8)
    agg_f16<8><<<(NN * 8 + 255) / 256, 256>>>(xh, aggh);
    gemm_f16<64, true, true, true><<<GEMM_GRID, 256, SMEM_SZ>>>(
        aggh, xh, wt + 0 * 16384, wt + 1 * 16384, b0, h0h);

    // layer 1: agg(h0_h) fp16 + h0_h self -> h1 fp16  (C=128 -> LPN=16)
    agg_f16<16><<<(NN * 16 + 255) / 256, 256>>>(h0h, aggh);
    gemm_f16<128, true, true, true><<<GEMM_GRID, 256, SMEM_SZ>>>(
        aggh, h0h, wt + 2 * 16384, wt + 3 * 16384, b1, h1h);

    // layer 2: transform-first. ts = h1 @ [Wl2 | Wr2] fp16 (cols 0-63 = t, 64-127 = s)
    gemm_f16<128, false, false, false><<<GEMM_GRID, 256, SMEM_SZ>>>(
        h1h, h1h, wt + 4 * 16384, wt + 4 * 16384, (const float*)0, tsh);

    // finalize layer 2 (64-wide fp16 gather) + classifier, fused
    finalize_classifier<<<(NN * 32 + 255) / 256, 256>>>(tsh, b2, Wc1, bc1, Wc2, bc2, out);
}

// round 14
// speedup vs baseline: 1.0348x; 1.0348x over previous
#include <cuda_runtime.h>
#include <cuda_fp16.h>
#include <math.h>
#include <stdint.h>

#define NN 50000
#define NE 640000
#define NNP 50048   // padded rows (GEMM tiles read up to 782*64)

// ---------------- scratch (static device globals; no allocation) ----------------
__device__ __half g_aggh[NNP * 128];        // fp16 aggregate buffer (width 64 or 128)
__device__ __half g_tsh[NNP * 128];         // fp16 layer-2 ts output
__device__ __half g_xh[NNP * 64];           // fp16 copy of x
__device__ __half g_h0h[NNP * 128];         // fp16 h0
__device__ __half g_h1h[NNP * 128];         // fp16 h1
__device__ float  g_invdeg[NN];
__device__ int    g_cnt[NN];
__device__ int    g_rowptr[NN];
__device__ int    g_cursor[NN];
__device__ int    g_srcidx[NE];
__device__ int    g_spine[128];
__device__ int    g_is64;
// transposed fp16 weights: slots 0-3 = Wl0,Wr0,Wl1,Wr1 ([N][K] k-major);
// slot 4 = concat [Wl2 rows 0-63 | Wr2 rows 64-127], K=128
__device__ __half g_wt[5][16384];

// ---------------- helpers ----------------
__device__ __forceinline__ uint32_t smem_u32(const void* p) {
    uint32_t a;
    asm("{ .reg .u64 t; cvta.to.shared.u64 t, %1; cvt.u32.u64 %0, t; }" : "=r"(a) : "l"(p));
    return a;
}
__device__ __forceinline__ void ldsm4(uint32_t& r0, uint32_t& r1, uint32_t& r2, uint32_t& r3,
                                      uint32_t addr) {
    asm volatile("ldmatrix.sync.aligned.m8n8.x4.shared.b16 {%0,%1,%2,%3}, [%4];"
                 : "=r"(r0), "=r"(r1), "=r"(r2), "=r"(r3) : "r"(addr));
}
__device__ __forceinline__ void mma_fp16(float* d, const uint32_t* a, const uint32_t* b) {
    asm volatile(
        "mma.sync.aligned.m16n8k16.row.col.f32.f16.f16.f32 "
        "{%0,%1,%2,%3}, {%4,%5,%6,%7}, {%8,%9}, {%0,%1,%2,%3};"
        : "+f"(d[0]), "+f"(d[1]), "+f"(d[2]), "+f"(d[3])
        : "r"(a[0]), "r"(a[1]), "r"(a[2]), "r"(a[3]), "r"(b[0]), "r"(b[1]));
}
__device__ __forceinline__ int sw128(int byte) { return byte ^ ((byte >> 3) & 0x70); }
__device__ __forceinline__ void cpasync16(uint32_t dst, const void* src) {
    asm volatile("cp.async.cg.shared.global [%0], [%1], 16;" :: "r"(dst), "l"(src));
}
#define CP_COMMIT() asm volatile("cp.async.commit_group;" ::: "memory")
#define CP_WAIT0()  asm volatile("cp.async.wait_group 0;" ::: "memory")

// ---------------- detect edge dtype + zero degree counters (merged) ----------------
__global__ void detect_zero(const int* __restrict__ w) {
    int i = blockIdx.x * blockDim.x + threadIdx.x;
    if (i < NN) g_cnt[i] = 0;
    if (blockIdx.x == 0) {
        __shared__ int flag;
        if (threadIdx.x == 0) flag = 0;
        __syncthreads();
        if (w[threadIdx.x * 2 + 1] != 0) atomicExch(&flag, 1);
        __syncthreads();
        if (threadIdx.x == 0) g_is64 = (flag == 0) ? 1 : 0;
    }
}

__device__ __forceinline__ int2 load_edge(const void* __restrict__ ei, int e) {
    int2 r;
    if (g_is64) {
        const long long* p = (const long long*)ei;
        r.x = (int)p[e];
        r.y = (int)p[NE + e];
    } else {
        const int* p = (const int*)ei;
        r.x = p[e];
        r.y = p[NE + e];
    }
    return r;
}

__global__ void count_deg(const void* __restrict__ ei) {
    int e = blockIdx.x * blockDim.x + threadIdx.x;
    if (e >= NE) return;
    int2 sd = load_edge(ei, e);
    atomicAdd(&g_cnt[sd.y], 1);
}

// phase 1: per-block (512) exclusive scan of g_cnt -> g_rowptr (local), totals -> g_spine
__global__ void scan1() {
    __shared__ int wsum[16];
    int i    = blockIdx.x * 512 + threadIdx.x;
    int lane = threadIdx.x & 31;
    int w    = threadIdx.x >> 5;
    int v    = (i < NN) ? g_cnt[i] : 0;
    int s    = v;
#pragma unroll
    for (int o = 1; o < 32; o <<= 1) {
        int t = __shfl_up_sync(0xffffffffu, s, o);
        if (lane >= o) s += t;
    }
    if (lane == 31) wsum[w] = s;
    __syncthreads();
    if (w == 0 && lane < 16) {
        int t = wsum[lane];
#pragma unroll
        for (int o = 1; o < 16; o <<= 1) {
            int u = __shfl_up_sync(0x0000ffffu, t, o);
            if (lane >= o) t += u;
        }
        wsum[lane] = t;
    }
    __syncthreads();
    int base = (w > 0) ? wsum[w - 1] : 0;
    if (i < NN) g_rowptr[i] = base + s - v;
    if (threadIdx.x == 0) g_spine[blockIdx.x] = wsum[15];
}

// phase 2+3 merged: warp 0 scans spine via shuffles (1 sync), all threads apply
__global__ void scan23(int nb) {
    __shared__ int sp[128];
    int t = threadIdx.x;
    if (t < 32) {
        int a0 = (4 * t + 0 < nb) ? g_spine[4 * t + 0] : 0;
        int a1 = (4 * t + 1 < nb) ? g_spine[4 * t + 1] : 0;
        int a2 = (4 * t + 2 < nb) ? g_spine[4 * t + 2] : 0;
        int a3 = (4 * t + 3 < nb) ? g_spine[4 * t + 3] : 0;
        int s1 = a0 + a1, s2 = s1 + a2, s3 = s2 + a3;
        int run = s3;
#pragma unroll
        for (int o = 1; o < 32; o <<= 1) {
            int u = __shfl_up_sync(0xffffffffu, run, o);
            if (t >= o) run += u;
        }
        int base = run - s3;
        sp[4 * t + 0] = base + a0;
        sp[4 * t + 1] = base + s1;
        sp[4 * t + 2] = base + s2;
        sp[4 * t + 3] = base + s3;
    }
    __syncthreads();
    int i = blockIdx.x * blockDim.x + t;
    if (i < NN) {
        int blk  = i >> 9;
        int excl = blk ? sp[blk - 1] : 0;
        int r    = g_rowptr[i] + excl;
        g_rowptr[i] = r;
        g_cursor[i] = r;
        g_invdeg[i] = 1.0f / fmaxf((float)g_cnt[i], 1.0f);
    }
}

__global__ void fill_csr(const void* __restrict__ ei) {
    int e = blockIdx.x * blockDim.x + threadIdx.x;
    if (e >= NE) return;
    int2 sd = load_edge(ei, e);
    int pos = atomicAdd(&g_cursor[sd.y], 1);
    g_srcidx[pos] = sd.x;
}

// ---------------- prep: weights transpose->fp16 (blocks 0-47) + x->fp16 (blocks 48+) ----------------
__global__ void prep(const float* __restrict__ x,
                     const float* W0, const float* W1, const float* W2,
                     const float* W3, const float* W4, const float* W5) {
    if (blockIdx.x < 48) {
        int b    = blockIdx.x >> 3;   // slot select 0..5
        int part = blockIdx.x & 7;
        const float* W;
        int K, N, slot, rofs;
        switch (b) {
            case 0: W = W0; K = 64;  N = 128; slot = 0; rofs = 0; break;
            case 1: W = W1; K = 64;  N = 128; slot = 1; rofs = 0; break;
            case 2: W = W2; K = 128; N = 128; slot = 2; rofs = 0; break;
            case 3: W = W3; K = 128; N = 128; slot = 3; rofs = 0; break;
            case 4: W = W4; K = 128; N = 64;  slot = 4; rofs = 0; break;   // Wl2 -> rows 0-63
            default: W = W5; K = 128; N = 64; slot = 4; rofs = 64; break;  // Wr2 -> rows 64-127
        }
        __half* dh = g_wt[slot] + rofs * 128;
        int total = K * N;
        for (int i = part * blockDim.x + threadIdx.x; i < total; i += 8 * blockDim.x) {
            int n = i / K, k = i % K;
            dh[i] = __float2half_rn(W[k * N + n]);
        }
    } else {
        int i = (blockIdx.x - 48) * blockDim.x + threadIdx.x;
        int stride = (gridDim.x - 48) * blockDim.x;
        for (; i < NN * 64; i += stride) g_xh[i] = __float2half_rn(x[i]);
    }
}

// ---------------- CSR mean-aggregation: one node per warp, G neighbor-groups ----------------
// CH = channels (halves). lanes split into G = 32/(CH/8) groups; group g handles
// neighbors g, g+G, ... with 16B loads; cross-group shfl reduce at the end.
template <int CH>
__global__ void agg_f16(const __half* __restrict__ feat, __half* __restrict__ out) {
    int gid  = blockIdx.x * blockDim.x + threadIdx.x;
    int node = gid >> 5;
    int lane = gid & 31;
    if (node >= NN) return;
    constexpr int LPG = CH / 8;     // lanes per group: 16 (CH=128) or 8 (CH=64)
    constexpr int G   = 32 / LPG;   // groups: 2 or 4
    const int grp = lane / LPG;
    const int col = (lane % LPG) * 8;

    const int* idx = g_srcidx + g_rowptr[node];
    const int  n   = g_cnt[node];
    float acc[8] = {0.f, 0.f, 0.f, 0.f, 0.f, 0.f, 0.f, 0.f};

    int j = grp;
    for (; j + G < n; j += 2 * G) {
        uint4 v0 = *(const uint4*)(feat + (size_t)idx[j] * CH + col);
        uint4 v1 = *(const uint4*)(feat + (size_t)idx[j + G] * CH + col);
        const uint32_t* w0 = (const uint32_t*)&v0;
        const uint32_t* w1 = (const uint32_t*)&v1;
#pragma unroll
        for (int k = 0; k < 4; k++) {
            float2 f0 = __half22float2(*(const __half2*)&w0[k]);
            float2 f1 = __half22float2(*(const __half2*)&w1[k]);
            acc[2 * k + 0] += f0.x + f1.x;
            acc[2 * k + 1] += f0.y + f1.y;
        }
    }
    if (j < n) {
        uint4 v0 = *(const uint4*)(feat + (size_t)idx[j] * CH + col);
        const uint32_t* w0 = (const uint32_t*)&v0;
#pragma unroll
        for (int k = 0; k < 4; k++) {
            float2 f0 = __half22float2(*(const __half2*)&w0[k]);
            acc[2 * k + 0] += f0.x;
            acc[2 * k + 1] += f0.y;
        }
    }

    // cross-group reduce: lanes i and i^off share the same column
#pragma unroll
    for (int off = 16; off >= LPG; off >>= 1)
#pragma unroll
        for (int k = 0; k < 8; k++)
            acc[k] += __shfl_xor_sync(0xffffffffu, acc[k], off);

    if (grp == 0) {
        float s = g_invdeg[node];
        uint4 o;
        uint32_t* ow = (uint32_t*)&o;
#pragma unroll
        for (int k = 0; k < 4; k++) {
            __half2 h = __float22half2_rn(make_float2(acc[2 * k] * s, acc[2 * k + 1] * s));
            ow[k] = *(uint32_t*)&h;
        }
        *(uint4*)(out + (size_t)node * CH + col) = o;
    }
}

// ---------------- pipelined warp-MMA GEMM, pure fp16 ----------------
// DUAL: out = A1 @ BL^T + A2 @ BR^T (+bias)(relu);  !DUAL: out = A1 @ BL^T
template <int KSRC, bool DUAL, bool RELU, bool BIAS>
__global__ __launch_bounds__(256, 2) void gemm_f16(
    const __half* __restrict__ A1, const __half* __restrict__ A2,
    const __half* __restrict__ BL, const __half* __restrict__ BR,
    const float* __restrict__ bias, __half* __restrict__ out) {
    extern __shared__ char smem[];
    // per-buffer: A 8K @0, B 16K @8192; buffer stride 24KB; total 48KB
    constexpr int BUF = 24576, BO = 8192;

    uint32_t sb = smem_u32(smem);
    const int tid = threadIdx.x, wid = tid >> 5, lid = tid & 31;
    const int wm = wid & 3, wn = wid >> 2;   // 4 x 2 warp grid over 64 x 128
    const int m0 = blockIdx.x * 64;

    constexpr int KH  = KSRC / 64;
    constexpr int NPH = DUAL ? 2 * KH : KH;

    float acc[8][4];
#pragma unroll
    for (int j = 0; j < 8; j++)
#pragma unroll
        for (int c = 0; c < 4; c++) acc[j][c] = 0.0f;

    auto gload = [&](int p) {
        const __half* A = (p < KH) ? A1 : A2;
        const __half* B = (p < KH) ? BL : BR;
        int kofs = (p % KH) * 64;
        int bb   = (p & 1) * BUF;
#pragma unroll
        for (int i = 0; i < 2; i++) {
            int idx = tid + i * 256;       // 0..511
            int r   = idx >> 3;            // row 0..63
            int c8  = idx & 7;
            int sw  = sw128(r * 128 + c8 * 16);
            cpasync16(sb + bb + sw, A + (size_t)(m0 + r) * KSRC + kofs + c8 * 8);
        }
#pragma unroll
        for (int i = 0; i < 4; i++) {
            int idx = tid + i * 256;       // 0..1023
            int r   = idx >> 3;            // row 0..127
            int c8  = idx & 7;
            int sw  = sw128(r * 128 + c8 * 16);
            cpasync16(sb + bb + BO + sw, B + (size_t)r * KSRC + kofs + c8 * 8);
        }
        CP_COMMIT();
    };

    auto compute = [&](int p) {
        int bb = (p & 1) * BUF;
#pragma unroll
        for (int ks = 0; ks < 4; ks++) {
            int k0b = ks * 32;
            uint32_t ah[4];
            {
                int mrow = wm * 16 + (lid & 15);
                int sw   = sw128(mrow * 128 + k0b + (lid >> 4) * 16);
                ldsm4(ah[0], ah[1], ah[2], ah[3], sb + bb + sw);
            }
#pragma unroll
            for (int ntp = 0; ntp < 4; ntp++) {
                int nrow = wn * 64 + ntp * 16 + ((lid >> 4) & 1) * 8 + (lid & 7);
                int sw   = sw128(nrow * 128 + k0b + ((lid >> 3) & 1) * 16);
                uint32_t bh[4];
                ldsm4(bh[0], bh[1], bh[2], bh[3], sb + bb + BO + sw);
#pragma unroll
                for (int j = 0; j < 2; j++)
                    mma_fp16(acc[ntp * 2 + j], ah, bh + 2 * j);
            }
        }
    };

    gload(0);
    CP_WAIT0();
    __syncthreads();
#pragma unroll 1
    for (int p = 0; p < NPH; p++) {
        if (p + 1 < NPH) gload(p + 1);
        compute(p);
        CP_WAIT0();
        __syncthreads();
    }

    // ---- epilogue (fp16 out) ----
    const int r  = lid >> 2;
    const int c2 = (lid & 3) * 2;
    int row0 = m0 + wm * 16 + r;
    int row1 = row0 + 8;
#pragma unroll
    for (int nt = 0; nt < 8; nt++) {
        int col = wn * 64 + nt * 8 + c2;
        float bx = BIAS ? __ldg(bias + col) : 0.f;
        float by = BIAS ? __ldg(bias + col + 1) : 0.f;
        float2 o0 = make_float2(acc[nt][0] + bx, acc[nt][1] + by);
        float2 o1 = make_float2(acc[nt][2] + bx, acc[nt][3] + by);
        if (RELU) {
            o0.x = fmaxf(o0.x, 0.f); o0.y = fmaxf(o0.y, 0.f);
            o1.x = fmaxf(o1.x, 0.f); o1.y = fmaxf(o1.y, 0.f);
        }
        if (row0 < NN) *(__half2*)(out + (size_t)row0 * 128 + col) = __float22half2_rn(o0);
        if (row1 < NN) *(__half2*)(out + (size_t)row1 * 128 + col) = __float22half2_rn(o1);
    }
}

// ---------------- layer-2 finalize + classifier (fused), warp per node ----------------
// ts: [NN][128] fp16; cols 0-63 = t = h1@Wl2 (to aggregate), cols 64-127 = s = h1@Wr2
__global__ void finalize_classifier(const __half* __restrict__ ts, const float* __restrict__ b2,
                                    const float* __restrict__ Wc1, const float* __restrict__ bc1,
                                    const float* __restrict__ Wc2, const float* __restrict__ bc2,
                                    float* __restrict__ out) {
    int gid  = blockIdx.x * blockDim.x + threadIdx.x;
    int node = gid >> 5;
    int lane = gid & 31;
    if (node >= NN) return;

    const int* idx = g_srcidx + g_rowptr[node];
    int n = g_cnt[node];
    float2 acc = make_float2(0.f, 0.f);
    int j = 0;
    for (; j + 4 <= n; j += 4) {
        int s0 = idx[j], s1 = idx[j + 1], s2 = idx[j + 2], s3 = idx[j + 3];
        float2 v0 = __half22float2(*(const __half2*)(ts + (size_t)s0 * 128 + lane * 2));
        float2 v1 = __half22float2(*(const __half2*)(ts + (size_t)s1 * 128 + lane * 2));
        float2 v2 = __half22float2(*(const __half2*)(ts + (size_t)s2 * 128 + lane * 2));
        float2 v3 = __half22float2(*(const __half2*)(ts + (size_t)s3 * 128 + lane * 2));
        acc.x += (v0.x + v1.x) + (v2.x + v3.x);
        acc.y += (v0.y + v1.y) + (v2.y + v3.y);
    }
    for (; j < n; j++) {
        float2 v = __half22float2(*(const __half2*)(ts + (size_t)idx[j] * 128 + lane * 2));
        acc.x += v.x; acc.y += v.y;
    }
    float sc = g_invdeg[node];
    float2 s = __half22float2(*(const __half2*)(ts + (size_t)node * 128 + 64 + lane * 2));
    float vx = acc.x * sc + s.x + __ldg(b2 + lane * 2);
    float vy = acc.y * sc + s.y + __ldg(b2 + lane * 2 + 1);

    float h = __ldg(bc1 + lane);
#pragma unroll
    for (int k = 0; k < 32; k++) {
        float ax = __shfl_sync(0xffffffffu, vx, k);
        float ay = __shfl_sync(0xffffffffu, vy, k);
        h = fmaf(ax, __ldg(Wc1 + (2 * k) * 32 + lane), h);
        h = fmaf(ay, __ldg(Wc1 + (2 * k + 1) * 32 + lane), h);
    }
    h = fmaxf(h, 0.0f);

    float p = h * __ldg(Wc2 + lane);
#pragma unroll
    for (int o = 16; o > 0; o >>= 1) p += __shfl_xor_sync(0xffffffffu, p, o);

    if (lane == 0) out[node] = 1.0f / (1.0f + expf(-(p + bc2[0])));
}

// ---------------- launch ----------------
extern "C" void kernel_launch(void* const* d_in, const int* in_sizes, int n_in,
                              void* d_out, int out_size) {
    const float* x   = (const float*)d_in[0];
    const void*  ei  = d_in[1];
    const float* Wl0 = (const float*)d_in[2];
    const float* Wr0 = (const float*)d_in[3];
    const float* b0  = (const float*)d_in[4];
    const float* Wl1 = (const float*)d_in[5];
    const float* Wr1 = (const float*)d_in[6];
    const float* b1  = (const float*)d_in[7];
    const float* Wl2 = (const float*)d_in[8];
    const float* Wr2 = (const float*)d_in[9];
    const float* b2  = (const float*)d_in[10];
    const float* Wc1 = (const float*)d_in[11];
    const float* bc1 = (const float*)d_in[12];
    const float* Wc2 = (const float*)d_in[13];
    const float* bc2 = (const float*)d_in[14];
    float* out = (float*)d_out;

    __half *aggh, *tsh, *xh, *h0h, *h1h, *wt;
    cudaGetSymbolAddress((void**)&aggh, g_aggh);
    cudaGetSymbolAddress((void**)&tsh, g_tsh);
    cudaGetSymbolAddress((void**)&xh, g_xh);
    cudaGetSymbolAddress((void**)&h0h, g_h0h);
    cudaGetSymbolAddress((void**)&h1h, g_h1h);
    cudaGetSymbolAddress((void**)&wt, g_wt);

    const int SMEM_SZ = 2 * 24576;  // 48KB (double-buffered 24KB stages)
    cudaFuncSetAttribute((void*)gemm_f16<64, true, true, true>,
                         cudaFuncAttributeMaxDynamicSharedMemorySize, SMEM_SZ);
    cudaFuncSetAttribute((void*)gemm_f16<128, true, true, true>,
                         cudaFuncAttributeMaxDynamicSharedMemorySize, SMEM_SZ);
    cudaFuncSetAttribute((void*)gemm_f16<128, false, false, false>,
                         cudaFuncAttributeMaxDynamicSharedMemorySize, SMEM_SZ);

    const int NB_SCAN = (NN + 511) / 512;  // 98

    // CSR build (ordered, scan-based — R10 structure)
    detect_zero<<<(NN + 255) / 256, 256>>>((const int*)ei);
    count_deg<<<(NE + 255) / 256, 256>>>(ei);
    scan1<<<NB_SCAN, 512>>>();
    scan23<<<(NN + 255) / 256, 256>>>(NB_SCAN);
    fill_csr<<<(NE + 255) / 256, 256>>>(ei);

    // weights -> fp16 transposed + x -> fp16, one kernel
    prep<<<48 + 1024, 256>>>(x, Wl0, Wr0, Wl1, Wr1, Wl2, Wr2);

    const int GEMM_GRID = (NNP + 63) / 64;  // 782

    // layer 0: agg(x_h) fp16 + x_h self -> h0 fp16   (CH=64: 4 groups x 8 lanes)
    agg_f16<64><<<(NN * 32 + 255) / 256, 256>>>(xh, aggh);
    gemm_f16<64, true, true, true><<<GEMM_GRID, 256, SMEM_SZ>>>(
        aggh, xh, wt + 0 * 16384, wt + 1 * 16384, b0, h0h);

    // layer 1: agg(h0_h) fp16 + h0_h self -> h1 fp16  (CH=128: 2 groups x 16 lanes)
    agg_f16<128><<<(NN * 32 + 255) / 256, 256>>>(h0h, aggh);
    gemm_f16<128, true, true, true><<<GEMM_GRID, 256, SMEM_SZ>>>(
        aggh, h0h, wt + 2 * 16384, wt + 3 * 16384, b1, h1h);

    // layer 2: transform-first. ts = h1 @ [Wl2 | Wr2] fp16 (cols 0-63 = t, 64-127 = s)
    gemm_f16<128, false, false, false><<<GEMM_GRID, 256, SMEM_SZ>>>(
        h1h, h1h, wt + 4 * 16384, wt + 4 * 16384, (const float*)0, tsh);

    // finalize layer 2 (64-wide fp16 gather) + classifier, fused
    finalize_classifier<<<(NN * 32 + 255) / 256, 256>>>(tsh, b2, Wc1, bc1, Wc2, bc2, out);
}

// round 17
// speedup vs baseline: 1.0653x; 1.0295x over previous
#include <cuda_runtime.h>
#include <cuda_fp16.h>
#include <math.h>
#include <stdint.h>

#define NN 50000
#define NE 640000
#define NNP 50048   // padded rows (GEMM tiles read up to 782*64)

// ---------------- scratch (static device globals; no allocation) ----------------
__device__ __half g_aggh[NNP * 128];        // fp16 aggregate buffer (width 64 or 128)
__device__ __half g_tsh[NNP * 128];         // fp16 layer-2 ts output
__device__ __half g_xh[NNP * 64];           // fp16 copy of x
__device__ __half g_h0h[NNP * 128];         // fp16 h0
__device__ __half g_h1h[NNP * 128];         // fp16 h1
__device__ float  g_invdeg[NN];
__device__ int    g_cnt[NN];
__device__ int    g_rowptr[NN];
__device__ int    g_cursor[NN];
__device__ int    g_srcidx[NE];
__device__ int    g_spine[128];
__device__ int    g_arrive;
__device__ int    g_flag;
__device__ int    g_is64;
// transposed fp16 weights: slots 0-3 = Wl0,Wr0,Wl1,Wr1 ([N][K] k-major);
// slot 4 = concat [Wl2 rows 0-63 | Wr2 rows 64-127], K=128
__device__ __half g_wt[5][16384];

// ---------------- helpers ----------------
__device__ __forceinline__ uint32_t smem_u32(const void* p) {
    uint32_t a;
    asm("{ .reg .u64 t; cvta.to.shared.u64 t, %1; cvt.u32.u64 %0, t; }" : "=r"(a) : "l"(p));
    return a;
}
__device__ __forceinline__ void ldsm4(uint32_t& r0, uint32_t& r1, uint32_t& r2, uint32_t& r3,
                                      uint32_t addr) {
    asm volatile("ldmatrix.sync.aligned.m8n8.x4.shared.b16 {%0,%1,%2,%3}, [%4];"
                 : "=r"(r0), "=r"(r1), "=r"(r2), "=r"(r3) : "r"(addr));
}
__device__ __forceinline__ void mma_fp16(float* d, const uint32_t* a, const uint32_t* b) {
    asm volatile(
        "mma.sync.aligned.m16n8k16.row.col.f32.f16.f16.f32 "
        "{%0,%1,%2,%3}, {%4,%5,%6,%7}, {%8,%9}, {%0,%1,%2,%3};"
        : "+f"(d[0]), "+f"(d[1]), "+f"(d[2]), "+f"(d[3])
        : "r"(a[0]), "r"(a[1]), "r"(a[2]), "r"(a[3]), "r"(b[0]), "r"(b[1]));
}
__device__ __forceinline__ int sw128(int byte) { return byte ^ ((byte >> 3) & 0x70); }
__device__ __forceinline__ void cpasync16(uint32_t dst, const void* src) {
    asm volatile("cp.async.cg.shared.global [%0], [%1], 16;" :: "r"(dst), "l"(src));
}
#define CP_COMMIT() asm volatile("cp.async.commit_group;" ::: "memory")
#define CP_WAIT0()  asm volatile("cp.async.wait_group 0;" ::: "memory")

// ---------------- detect edge dtype + zero degree counters (merged) ----------------
__global__ void detect_zero(const int* __restrict__ w) {
    int i = blockIdx.x * blockDim.x + threadIdx.x;
    if (i < NN) g_cnt[i] = 0;
    if (i == 0) { g_arrive = 0; g_flag = 0; }
    if (blockIdx.x == 0) {
        __shared__ int flag;
        if (threadIdx.x == 0) flag = 0;
        __syncthreads();
        if (w[threadIdx.x * 2 + 1] != 0) atomicExch(&flag, 1);
        __syncthreads();
        if (threadIdx.x == 0) g_is64 = (flag == 0) ? 1 : 0;
    }
}

__device__ __forceinline__ int2 load_edge(const void* __restrict__ ei, int e) {
    int2 r;
    if (g_is64) {
        const long long* p = (const long long*)ei;
        r.x = (int)p[e];
        r.y = (int)p[NE + e];
    } else {
        const int* p = (const int*)ei;
        r.x = p[e];
        r.y = p[NE + e];
    }
    return r;
}

__global__ void count_deg(const void* __restrict__ ei) {
    int e = blockIdx.x * blockDim.x + threadIdx.x;
    if (e >= NE) return;
    int2 sd = load_edge(ei, e);
    atomicAdd(&g_cnt[sd.y], 1);
}

// ---------------- single-kernel grid-wide exclusive scan (98 co-resident blocks) ----------------
// Each block: local scan of 512 counts; publish total; last-arriving block scans
// the spine and raises the flag; others spin (all blocks resident -> no deadlock);
// then everyone applies its exclusive base and writes rowptr/cursor/invdeg.
__global__ void scan_all(int nb) {
    __shared__ int wsum[16];
    __shared__ int s_last;
    __shared__ int s_excl;
    int i    = blockIdx.x * 512 + threadIdx.x;
    int tid  = threadIdx.x;
    int lane = tid & 31;
    int w    = tid >> 5;
    int v    = (i < NN) ? g_cnt[i] : 0;
    int s    = v;
#pragma unroll
    for (int o = 1; o < 32; o <<= 1) {
        int t = __shfl_up_sync(0xffffffffu, s, o);
        if (lane >= o) s += t;
    }
    if (lane == 31) wsum[w] = s;
    __syncthreads();
    if (w == 0 && lane < 16) {
        int t = wsum[lane];
#pragma unroll
        for (int o = 1; o < 16; o <<= 1) {
            int u = __shfl_up_sync(0x0000ffffu, t, o);
            if (lane >= o) t += u;
        }
        wsum[lane] = t;
    }
    __syncthreads();
    int base  = (w > 0) ? wsum[w - 1] : 0;
    int local = base + s - v;   // exclusive within block

    if (tid == 0) {
        g_spine[blockIdx.x] = wsum[15];
        __threadfence();
        int a = atomicAdd(&g_arrive, 1);
        s_last = (a == nb - 1) ? 1 : 0;
    }
    __syncthreads();

    if (s_last) {
        // last block: inclusive-scan the spine in place
        if (tid < 32) {
            int a0 = (4 * tid + 0 < nb) ? g_spine[4 * tid + 0] : 0;
            int a1 = (4 * tid + 1 < nb) ? g_spine[4 * tid + 1] : 0;
            int a2 = (4 * tid + 2 < nb) ? g_spine[4 * tid + 2] : 0;
            int a3 = (4 * tid + 3 < nb) ? g_spine[4 * tid + 3] : 0;
            int s1 = a0 + a1, s2 = s1 + a2, s3 = s2 + a3;
            int run = s3;
#pragma unroll
            for (int o = 1; o < 32; o <<= 1) {
                int u = __shfl_up_sync(0xffffffffu, run, o);
                if (lane >= o) run += u;
            }
            int b0 = run - s3;
            g_spine[4 * tid + 0] = b0 + a0;
            g_spine[4 * tid + 1] = b0 + s1;
            g_spine[4 * tid + 2] = b0 + s2;
            g_spine[4 * tid + 3] = b0 + s3;
        }
        __syncthreads();
        if (tid == 0) {
            __threadfence();
            atomicExch(&g_flag, 1);
        }
    } else {
        if (tid == 0)
            while (atomicAdd(&g_flag, 0) == 0) { }
        __syncthreads();
    }

    if (tid == 0)
        s_excl = blockIdx.x ? atomicAdd(&g_spine[blockIdx.x - 1], 0) : 0;
    __syncthreads();

    if (i < NN) {
        int r = s_excl + local;
        g_rowptr[i] = r;
        g_cursor[i] = r;
        g_invdeg[i] = 1.0f / fmaxf((float)v, 1.0f);
    }
}

__global__ void fill_csr(const void* __restrict__ ei) {
    int e = blockIdx.x * blockDim.x + threadIdx.x;
    if (e >= NE) return;
    int2 sd = load_edge(ei, e);
    int pos = atomicAdd(&g_cursor[sd.y], 1);
    g_srcidx[pos] = sd.x;
}

// ---------------- prep: weights transpose->fp16 (blocks 0-47) + x->fp16 (blocks 48+) ----------------
__global__ void prep(const float* __restrict__ x,
                     const float* W0, const float* W1, const float* W2,
                     const float* W3, const float* W4, const float* W5) {
    if (blockIdx.x < 48) {
        int b    = blockIdx.x >> 3;   // slot select 0..5
        int part = blockIdx.x & 7;
        const float* W;
        int K, N, slot, rofs;
        switch (b) {
            case 0: W = W0; K = 64;  N = 128; slot = 0; rofs = 0; break;
            case 1: W = W1; K = 64;  N = 128; slot = 1; rofs = 0; break;
            case 2: W = W2; K = 128; N = 128; slot = 2; rofs = 0; break;
            case 3: W = W3; K = 128; N = 128; slot = 3; rofs = 0; break;
            case 4: W = W4; K = 128; N = 64;  slot = 4; rofs = 0; break;   // Wl2 -> rows 0-63
            default: W = W5; K = 128; N = 64; slot = 4; rofs = 64; break;  // Wr2 -> rows 64-127
        }
        __half* dh = g_wt[slot] + rofs * 128;
        int total = K * N;
        for (int i = part * blockDim.x + threadIdx.x; i < total; i += 8 * blockDim.x) {
            int n = i / K, k = i % K;
            dh[i] = __float2half_rn(W[k * N + n]);
        }
    } else {
        int i = (blockIdx.x - 48) * blockDim.x + threadIdx.x;
        int stride = (gridDim.x - 48) * blockDim.x;
        for (; i < NN * 64; i += stride) g_xh[i] = __float2half_rn(x[i]);
    }
}

// ---------------- CSR mean-aggregation over fp16 features, fp16 out (R10 proven) ----------------
// LPN lanes per node, each lane owns 4 channels (C = LPN*4)
template <int LPN>
__global__ void agg_f16(const __half* __restrict__ feat, __half* __restrict__ out) {
    int gid  = blockIdx.x * blockDim.x + threadIdx.x;
    int node = gid / LPN;
    int lane = gid % LPN;
    if (node >= NN) return;
    const int  C   = LPN * 4;
    const int* idx = g_srcidx + g_rowptr[node];
    int        n   = g_cnt[node];
    float4 acc = make_float4(0.f, 0.f, 0.f, 0.f);
    int j = 0;
    for (; j + 4 <= n; j += 4) {
        int s0 = idx[j], s1 = idx[j + 1], s2 = idx[j + 2], s3 = idx[j + 3];
        __half2 a0 = *(const __half2*)(feat + (size_t)s0 * C + lane * 4);
        __half2 b0 = *(const __half2*)(feat + (size_t)s0 * C + lane * 4 + 2);
        __half2 a1 = *(const __half2*)(feat + (size_t)s1 * C + lane * 4);
        __half2 b1 = *(const __half2*)(feat + (size_t)s1 * C + lane * 4 + 2);
        __half2 a2 = *(const __half2*)(feat + (size_t)s2 * C + lane * 4);
        __half2 b2 = *(const __half2*)(feat + (size_t)s2 * C + lane * 4 + 2);
        __half2 a3 = *(const __half2*)(feat + (size_t)s3 * C + lane * 4);
        __half2 b3 = *(const __half2*)(feat + (size_t)s3 * C + lane * 4 + 2);
        float2 f0 = __half22float2(a0), g0 = __half22float2(b0);
        float2 f1 = __half22float2(a1), g1 = __half22float2(b1);
        float2 f2 = __half22float2(a2), g2 = __half22float2(b2);
        float2 f3 = __half22float2(a3), g3 = __half22float2(b3);
        acc.x += (f0.x + f1.x) + (f2.x + f3.x);
        acc.y += (f0.y + f1.y) + (f2.y + f3.y);
        acc.z += (g0.x + g1.x) + (g2.x + g3.x);
        acc.w += (g0.y + g1.y) + (g2.y + g3.y);
    }
    for (; j < n; j++) {
        int s0 = idx[j];
        __half2 a0 = *(const __half2*)(feat + (size_t)s0 * C + lane * 4);
        __half2 b0 = *(const __half2*)(feat + (size_t)s0 * C + lane * 4 + 2);
        float2 f0 = __half22float2(a0), g0 = __half22float2(b0);
        acc.x += f0.x; acc.y += f0.y; acc.z += g0.x; acc.w += g0.y;
    }
    float s = g_invdeg[node];
    __half2 o01 = __float22half2_rn(make_float2(acc.x * s, acc.y * s));
    __half2 o23 = __float22half2_rn(make_float2(acc.z * s, acc.w * s));
    uint2 pack;
    pack.x = *(uint32_t*)&o01;
    pack.y = *(uint32_t*)&o23;
    *(uint2*)(out + (size_t)node * C + lane * 4) = pack;
}

// ---------------- pipelined warp-MMA GEMM, pure fp16 ----------------
// DUAL: out = A1 @ BL^T + A2 @ BR^T (+bias)(relu);  !DUAL: out = A1 @ BL^T
template <int KSRC, bool DUAL, bool RELU, bool BIAS>
__global__ __launch_bounds__(256, 2) void gemm_f16(
    const __half* __restrict__ A1, const __half* __restrict__ A2,
    const __half* __restrict__ BL, const __half* __restrict__ BR,
    const float* __restrict__ bias, __half* __restrict__ out) {
    extern __shared__ char smem[];
    // per-buffer: A 8K @0, B 16K @8192; buffer stride 24KB; total 48KB
    constexpr int BUF = 24576, BO = 8192;

    uint32_t sb = smem_u32(smem);
    const int tid = threadIdx.x, wid = tid >> 5, lid = tid & 31;
    const int wm = wid & 3, wn = wid >> 2;   // 4 x 2 warp grid over 64 x 128
    const int m0 = blockIdx.x * 64;

    constexpr int KH  = KSRC / 64;
    constexpr int NPH = DUAL ? 2 * KH : KH;

    float acc[8][4];
#pragma unroll
    for (int j = 0; j < 8; j++)
#pragma unroll
        for (int c = 0; c < 4; c++) acc[j][c] = 0.0f;

    auto gload = [&](int p) {
        const __half* A = (p < KH) ? A1 : A2;
        const __half* B = (p < KH) ? BL : BR;
        int kofs = (p % KH) * 64;
        int bb   = (p & 1) * BUF;
#pragma unroll
        for (int i = 0; i < 2; i++) {
            int idx = tid + i * 256;       // 0..511
            int r   = idx >> 3;            // row 0..63
            int c8  = idx & 7;
            int sw  = sw128(r * 128 + c8 * 16);
            cpasync16(sb + bb + sw, A + (size_t)(m0 + r) * KSRC + kofs + c8 * 8);
        }
#pragma unroll
        for (int i = 0; i < 4; i++) {
            int idx = tid + i * 256;       // 0..1023
            int r   = idx >> 3;            // row 0..127
            int c8  = idx & 7;
            int sw  = sw128(r * 128 + c8 * 16);
            cpasync16(sb + bb + BO + sw, B + (size_t)r * KSRC + kofs + c8 * 8);
        }
        CP_COMMIT();
    };

    auto compute = [&](int p) {
        int bb = (p & 1) * BUF;
#pragma unroll
        for (int ks = 0; ks < 4; ks++) {
            int k0b = ks * 32;
            uint32_t ah[4];
            {
                int mrow = wm * 16 + (lid & 15);
                int sw   = sw128(mrow * 128 + k0b + (lid >> 4) * 16);
                ldsm4(ah[0], ah[1], ah[2], ah[3], sb + bb + sw);
            }
#pragma unroll
            for (int ntp = 0; ntp < 4; ntp++) {
                int nrow = wn * 64 + ntp * 16 + ((lid >> 4) & 1) * 8 + (lid & 7);
                int sw   = sw128(nrow * 128 + k0b + ((lid >> 3) & 1) * 16);
                uint32_t bh[4];
                ldsm4(bh[0], bh[1], bh[2], bh[3], sb + bb + BO + sw);
#pragma unroll
                for (int j = 0; j < 2; j++)
                    mma_fp16(acc[ntp * 2 + j], ah, bh + 2 * j);
            }
        }
    };

    gload(0);
    CP_WAIT0();
    __syncthreads();
#pragma unroll 1
    for (int p = 0; p < NPH; p++) {
        if (p + 1 < NPH) gload(p + 1);
        compute(p);
        CP_WAIT0();
        __syncthreads();
    }

    // ---- epilogue (fp16 out) ----
    const int r  = lid >> 2;
    const int c2 = (lid & 3) * 2;
    int row0 = m0 + wm * 16 + r;
    int row1 = row0 + 8;
#pragma unroll
    for (int nt = 0; nt < 8; nt++) {
        int col = wn * 64 + nt * 8 + c2;
        float bx = BIAS ? __ldg(bias + col) : 0.f;
        float by = BIAS ? __ldg(bias + col + 1) : 0.f;
        float2 o0 = make_float2(acc[nt][0] + bx, acc[nt][1] + by);
        float2 o1 = make_float2(acc[nt][2] + bx, acc[nt][3] + by);
        if (RELU) {
            o0.x = fmaxf(o0.x, 0.f); o0.y = fmaxf(o0.y, 0.f);
            o1.x = fmaxf(o1.x, 0.f); o1.y = fmaxf(o1.y, 0.f);
        }
        if (row0 < NN) *(__half2*)(out + (size_t)row0 * 128 + col) = __float22half2_rn(o0);
        if (row1 < NN) *(__half2*)(out + (size_t)row1 * 128 + col) = __float22half2_rn(o1);
    }
}

// ---------------- layer-2 finalize + classifier (fused), warp per node ----------------
// ts: [NN][128] fp16; cols 0-63 = t = h1@Wl2 (to aggregate), cols 64-127 = s = h1@Wr2
__global__ void finalize_classifier(const __half* __restrict__ ts, const float* __restrict__ b2,
                                    const float* __restrict__ Wc1, const float* __restrict__ bc1,
                                    const float* __restrict__ Wc2, const float* __restrict__ bc2,
                                    float* __restrict__ out) {
    int gid  = blockIdx.x * blockDim.x + threadIdx.x;
    int node = gid >> 5;
    int lane = gid & 31;
    if (node >= NN) return;

    const int* idx = g_srcidx + g_rowptr[node];
    int n = g_cnt[node];
    float2 acc = make_float2(0.f, 0.f);
    int j = 0;
    for (; j + 4 <= n; j += 4) {
        int s0 = idx[j], s1 = idx[j + 1], s2 = idx[j + 2], s3 = idx[j + 3];
        float2 v0 = __half22float2(*(const __half2*)(ts + (size_t)s0 * 128 + lane * 2));
        float2 v1 = __half22float2(*(const __half2*)(ts + (size_t)s1 * 128 + lane * 2));
        float2 v2 = __half22float2(*(const __half2*)(ts + (size_t)s2 * 128 + lane * 2));
        float2 v3 = __half22float2(*(const __half2*)(ts + (size_t)s3 * 128 + lane * 2));
        acc.x += (v0.x + v1.x) + (v2.x + v3.x);
        acc.y += (v0.y + v1.y) + (v2.y + v3.y);
    }
    for (; j < n; j++) {
        float2 v = __half22float2(*(const __half2*)(ts + (size_t)idx[j] * 128 + lane * 2));
        acc.x += v.x; acc.y += v.y;
    }
    float sc = g_invdeg[node];
    float2 s = __half22float2(*(const __half2*)(ts + (size_t)node * 128 + 64 + lane * 2));
    float vx = acc.x * sc + s.x + __ldg(b2 + lane * 2);
    float vy = acc.y * sc + s.y + __ldg(b2 + lane * 2 + 1);

    float h = __ldg(bc1 + lane);
#pragma unroll
    for (int k = 0; k < 32; k++) {
        float ax = __shfl_sync(0xffffffffu, vx, k);
        float ay = __shfl_sync(0xffffffffu, vy, k);
        h = fmaf(ax, __ldg(Wc1 + (2 * k) * 32 + lane), h);
        h = fmaf(ay, __ldg(Wc1 + (2 * k + 1) * 32 + lane), h);
    }
    h = fmaxf(h, 0.0f);

    float p = h * __ldg(Wc2 + lane);
#pragma unroll
    for (int o = 16; o > 0; o >>= 1) p += __shfl_xor_sync(0xffffffffu, p, o);

    if (lane == 0) out[node] = 1.0f / (1.0f + expf(-(p + bc2[0])));
}

// ---------------- launch ----------------
extern "C" void kernel_launch(void* const* d_in, const int* in_sizes, int n_in,
                              void* d_out, int out_size) {
    const float* x   = (const float*)d_in[0];
    const void*  ei  = d_in[1];
    const float* Wl0 = (const float*)d_in[2];
    const float* Wr0 = (const float*)d_in[3];
    const float* b0  = (const float*)d_in[4];
    const float* Wl1 = (const float*)d_in[5];
    const float* Wr1 = (const float*)d_in[6];
    const float* b1  = (const float*)d_in[7];
    const float* Wl2 = (const float*)d_in[8];
    const float* Wr2 = (const float*)d_in[9];
    const float* b2  = (const float*)d_in[10];
    const float* Wc1 = (const float*)d_in[11];
    const float* bc1 = (const float*)d_in[12];
    const float* Wc2 = (const float*)d_in[13];
    const float* bc2 = (const float*)d_in[14];
    float* out = (float*)d_out;

    __half *aggh, *tsh, *xh, *h0h, *h1h, *wt;
    cudaGetSymbolAddress((void**)&aggh, g_aggh);
    cudaGetSymbolAddress((void**)&tsh, g_tsh);
    cudaGetSymbolAddress((void**)&xh, g_xh);
    cudaGetSymbolAddress((void**)&h0h, g_h0h);
    cudaGetSymbolAddress((void**)&h1h, g_h1h);
    cudaGetSymbolAddress((void**)&wt, g_wt);

    const int SMEM_SZ = 2 * 24576;  // 48KB (double-buffered 24KB stages)
    cudaFuncSetAttribute((void*)gemm_f16<64, true, true, true>,
                         cudaFuncAttributeMaxDynamicSharedMemorySize, SMEM_SZ);
    cudaFuncSetAttribute((void*)gemm_f16<128, true, true, true>,
                         cudaFuncAttributeMaxDynamicSharedMemorySize, SMEM_SZ);
    cudaFuncSetAttribute((void*)gemm_f16<128, false, false, false>,
                         cudaFuncAttributeMaxDynamicSharedMemorySize, SMEM_SZ);

    const int NB_SCAN = (NN + 511) / 512;  // 98 (co-resident -> scan_all rendezvous safe)

    // CSR build (ordered; single-kernel scan)
    detect_zero<<<(NN + 255) / 256, 256>>>((const int*)ei);
    count_deg<<<(NE + 255) / 256, 256>>>(ei);
    scan_all<<<NB_SCAN, 512>>>(NB_SCAN);
    fill_csr<<<(NE + 255) / 256, 256>>>(ei);

    // weights -> fp16 transposed + x -> fp16, one kernel
    prep<<<48 + 1024, 256>>>(x, Wl0, Wr0, Wl1, Wr1, Wl2, Wr2);

    const int GEMM_GRID = (NNP + 63) / 64;  // 782

    // layer 0: agg(x_h) fp16 + x_h self -> h0 fp16   (C=64 -> LPN=16)
    agg_f16<16><<<(NN * 16 + 255) / 256, 256>>>(xh, aggh);
    gemm_f16<64, true, true, true><<<GEMM_GRID, 256, SMEM_SZ>>>(
        aggh, xh, wt + 0 * 16384, wt + 1 * 16384, b0, h0h);

    // layer 1: agg(h0_h) fp16 + h0_h self -> h1 fp16  (C=128 -> LPN=32)
    agg_f16<32><<<(NN * 32 + 255) / 256, 256>>>(h0h, aggh);
    gemm_f16<128, true, true, true><<<GEMM_GRID, 256, SMEM_SZ>>>(
        aggh, h0h, wt + 2 * 16384, wt + 3 * 16384, b1, h1h);

    // layer 2: transform-first. ts = h1 @ [Wl2 | Wr2] fp16 (cols 0-63 = t, 64-127 = s)
    gemm_f16<128, false, false, false><<<GEMM_GRID, 256, SMEM_SZ>>>(
        h1h, h1h, wt + 4 * 16384, wt + 4 * 16384, (const float*)0, tsh);

    // finalize layer 2 (64-wide fp16 gather) + classifier, fused
    finalize_classifier<<<(NN * 32 + 255) / 256, 256>>>(tsh, b2, Wc1, bc1, Wc2, bc2, out);
}